// round 1
// baseline (speedup 1.0000x reference)
#include <cuda_runtime.h>
#include <math.h>

#define NN 100000
#define NE 1600000
#define NG 512
#define HID 64

// ---------------- device scratch (static; no runtime allocation) ----------------
__device__ int   g_is64;
__device__ int   g_src[NE];
__device__ int   g_dst[NE];
__device__ int   g_bat[NN];
__device__ float g_bufA[NN * HID];
__device__ float g_bufB[NN * HID];
__device__ float g_agg [NN * HID];
__device__ float g_sums[NG * 16];
__device__ float g_cnts[NG];

// ---------------- dtype detection: int64 edge_index has zero high words ---------
__global__ void k_detect(const unsigned int* __restrict__ ei) {
    if (blockIdx.x == 0 && threadIdx.x == 0) {
        int is64 = 1;
        #pragma unroll 1
        for (int i = 1; i < 128; i += 2) {
            if (ei[i] != 0u) { is64 = 0; break; }
        }
        g_is64 = is64;
    }
}

// ---------------- normalize indices to int32 scratch ----------------------------
__global__ void k_convert(const void* __restrict__ ei_, const void* __restrict__ bat_) {
    int t = blockIdx.x * blockDim.x + threadIdx.x;
    int is64 = g_is64;
    if (t < NE) {
        if (is64) {
            const long long* e = (const long long*)ei_;
            g_src[t] = (int)e[t];
            g_dst[t] = (int)e[NE + t];
        } else {
            const int* e = (const int*)ei_;
            g_src[t] = e[t];
            g_dst[t] = e[NE + t];
        }
    }
    if (t < NN) {
        if (is64) g_bat[t] = (int)((const long long*)bat_)[t];
        else      g_bat[t] = ((const int*)bat_)[t];
    }
}

// ---------------- h0 = x @ W0 + b0   (N x 11 @ 11 x 64) -------------------------
__global__ void __launch_bounds__(256) k_lin0(const float* __restrict__ x,
                                              const float* __restrict__ W0,
                                              const float* __restrict__ b0) {
    __shared__ float sW[11 * 64];
    __shared__ float sB[64];
    int t = threadIdx.x;
    for (int i = t; i < 11 * 64; i += 256) sW[i] = W0[i];
    if (t < 64) sB[t] = b0[t];
    __syncthreads();

    int gid = blockIdx.x * 256 + t;      // gid < NN*64 (exact multiple of 256)
    int n = gid >> 6, j = gid & 63;
    const float* xr = x + n * 11;
    float acc = sB[j];
    #pragma unroll
    for (int k = 0; k < 11; k++) acc += xr[k] * sW[k * 64 + j];
    g_bufA[gid] = acc;
}

// ---------------- zero agg (and pool accumulators on first pass) ----------------
__global__ void k_zero(int zero_pool) {
    int t = blockIdx.x * blockDim.x + threadIdx.x;
    if (t < NN * HID) g_agg[t] = 0.0f;
    if (zero_pool) {
        if (t < NG * 16) g_sums[t] = 0.0f;
        if (t < NG)      g_cnts[t] = 0.0f;
    }
}

// ---------------- edge scatter: agg[dst] += h[src], vector atomics --------------
__global__ void __launch_bounds__(256) k_scatter(int in_sel) {
    const float* __restrict__ h = in_sel ? g_bufB : g_bufA;
    int t = blockIdx.x * blockDim.x + threadIdx.x;   // t < NE*16
    int e = t >> 4, c = t & 15;
    int s = g_src[e];
    int d = g_dst[e];
    float4 v = ((const float4*)h)[s * 16 + c];
    float4* p = ((float4*)g_agg) + d * 16 + c;
    asm volatile("red.global.add.v4.f32 [%0], {%1,%2,%3,%4};"
                 :: "l"(p), "f"(v.x), "f"(v.y), "f"(v.z), "f"(v.w)
                 : "memory");
}

// ---------------- conv: h_out = tanh(agg @ Wrel + brel + h_in @ Wroot) ----------
__global__ void __launch_bounds__(256) k_conv(int in_sel,
                                              const float* __restrict__ Wrel,
                                              const float* __restrict__ brel,
                                              const float* __restrict__ Wroot,
                                              int out_sel) {
    __shared__ __align__(16) float sWr[64 * 64];
    __shared__ __align__(16) float sWo[64 * 64];
    __shared__ float sA[16][68];   // padded: avoid bank conflicts on broadcast pairs
    __shared__ float sH[16][68];
    __shared__ float sB[64];

    const float* __restrict__ hin  = in_sel  ? g_bufB : g_bufA;
    float* __restrict__       hout = out_sel ? g_bufB : g_bufA;

    int t = threadIdx.x;
    const float4* Wr4 = (const float4*)Wrel;
    const float4* Wo4 = (const float4*)Wroot;
    float4* sWr4 = (float4*)sWr;
    float4* sWo4 = (float4*)sWo;
    #pragma unroll
    for (int i = t; i < 1024; i += 256) { sWr4[i] = Wr4[i]; sWo4[i] = Wo4[i]; }
    if (t < 64) sB[t] = brel[t];

    int n0 = blockIdx.x * 16;      // NN/16 = 6250 blocks, exact
    for (int i = t; i < 1024; i += 256) {
        int n = i >> 6, k = i & 63;
        sA[n][k] = g_agg[(n0 + n) * 64 + k];
        sH[n][k] = hin  [(n0 + n) * 64 + k];
    }
    __syncthreads();

    int ln = t >> 4, jq = t & 15, j0 = jq * 4;
    float4 acc = make_float4(sB[j0], sB[j0 + 1], sB[j0 + 2], sB[j0 + 3]);
    #pragma unroll 8
    for (int k = 0; k < 64; k++) {
        float a = sA[ln][k];
        float h = sH[ln][k];
        float4 wr = *(const float4*)&sWr[k * 64 + j0];
        float4 wo = *(const float4*)&sWo[k * 64 + j0];
        acc.x += a * wr.x + h * wo.x;
        acc.y += a * wr.y + h * wo.y;
        acc.z += a * wr.z + h * wo.z;
        acc.w += a * wr.w + h * wo.w;
    }
    float4 o = make_float4(tanhf(acc.x), tanhf(acc.y), tanhf(acc.z), tanhf(acc.w));
    *(float4*)&hout[(n0 + ln) * 64 + j0] = o;
}

// -------- h3 = tanh(h2 @ W3 + b3); pooled sums/counts via global atomics --------
__global__ void __launch_bounds__(256) k_lin3pool(const float* __restrict__ W3,
                                                  const float* __restrict__ b3) {
    __shared__ float sW[64 * 16];
    __shared__ float sB[16];
    int t = threadIdx.x;
    for (int i = t; i < 64 * 16; i += 256) sW[i] = W3[i];
    if (t < 16) sB[t] = b3[t];
    __syncthreads();

    int gid = blockIdx.x * 256 + t;    // gid < NN*16, exact multiple of 256
    int n = gid >> 4, j = gid & 15;
    const float* hr = g_bufA + n * 64;   // h2 lives in bufA
    float acc = sB[j];
    #pragma unroll
    for (int k = 0; k < 64; k++) acc += hr[k] * sW[k * 16 + j];
    float v = tanhf(acc);
    int g = g_bat[n];
    atomicAdd(&g_sums[g * 16 + j], v);
    if (j == 0) atomicAdd(&g_cnts[g], 1.0f);
}

// ---------------- mean pool + NormalParamExtractor -------------------------------
__global__ void k_final(float* __restrict__ out) {
    int t = blockIdx.x * blockDim.x + threadIdx.x;
    if (t >= NG * 16) return;
    int g = t >> 4, j = t & 15;
    float m = g_sums[t] / fmaxf(g_cnts[g], 1.0f);
    if (j < 8) {
        out[g * 8 + j] = m;                       // loc
    } else {
        float s = m + 0.54132485461292192f;       // log(expm1(1.0))
        float sp = (s > 20.0f) ? s : log1pf(expf(s));
        out[NG * 8 + g * 8 + (j - 8)] = fmaxf(sp, 1e-4f);   // scale
    }
}

// ---------------- launch ---------------------------------------------------------
extern "C" void kernel_launch(void* const* d_in, const int* in_sizes, int n_in,
                              void* d_out, int out_size) {
    const float* x     = (const float*)d_in[0];
    const void*  ei    = d_in[1];
    const void*  bat   = d_in[2];
    const float* W0    = (const float*)d_in[3];
    const float* b0    = (const float*)d_in[4];
    const float* Wrel1 = (const float*)d_in[5];
    const float* brel1 = (const float*)d_in[6];
    const float* Wroot1= (const float*)d_in[7];
    const float* Wrel2 = (const float*)d_in[8];
    const float* brel2 = (const float*)d_in[9];
    const float* Wroot2= (const float*)d_in[10];
    const float* W3    = (const float*)d_in[11];
    const float* b3    = (const float*)d_in[12];
    float* out = (float*)d_out;

    k_detect<<<1, 32>>>((const unsigned int*)ei);
    k_convert<<<(NE + 255) / 256, 256>>>(ei, bat);

    k_lin0<<<NN * 64 / 256, 256>>>(x, W0, b0);          // h0 -> bufA
    k_zero<<<NN * HID / 256, 256>>>(1);                 // agg=0, sums=0, cnts=0

    k_scatter<<<NE * 16 / 256, 256>>>(0);               // agg += h0[src]
    k_conv<<<NN / 16, 256>>>(0, Wrel1, brel1, Wroot1, 1); // h1 -> bufB

    k_zero<<<NN * HID / 256, 256>>>(0);                 // agg=0
    k_scatter<<<NE * 16 / 256, 256>>>(1);               // agg += h1[src]
    k_conv<<<NN / 16, 256>>>(1, Wrel2, brel2, Wroot2, 0); // h2 -> bufA

    k_lin3pool<<<NN * 16 / 256, 256>>>(W3, b3);         // sums/cnts
    k_final<<<(NG * 16 + 255) / 256, 256>>>(out);
}

// round 2
// speedup vs baseline: 1.2059x; 1.2059x over previous
#include <cuda_runtime.h>
#include <math.h>

#define NN 100000
#define NE 1600000
#define NG 512

// ---------------- device scratch ----------------
__device__ int   g_is64;
__device__ float g_bufA[NN * 64];
__device__ float g_bufB[NN * 64];
__device__ float g_agg [NN * 64];
__device__ float g_sums[NG * 16];
__device__ float g_cnts[NG];

// ---------------- packed fp32x2 helpers (PTX-only on sm_103a) -------------------
__device__ __forceinline__ unsigned long long fma2(unsigned long long a,
                                                   unsigned long long b,
                                                   unsigned long long c) {
    unsigned long long d;
    asm("fma.rn.f32x2 %0, %1, %2, %3;" : "=l"(d) : "l"(a), "l"(b), "l"(c));
    return d;
}
__device__ __forceinline__ unsigned long long dup2(float a) {
    unsigned long long d;
    asm("mov.b64 %0, {%1, %1};" : "=l"(d) : "f"(a));
    return d;
}

// ---------------- dtype detection: int64 edge_index has zero high words ---------
__global__ void k_detect(const unsigned int* __restrict__ ei) {
    if (threadIdx.x == 0) {
        int is64 = 1;
        #pragma unroll 1
        for (int i = 1; i < 128; i += 2) {
            if (ei[i] != 0u) { is64 = 0; break; }
        }
        g_is64 = is64;
    }
}

// ------- h0 = x @ W0 + b0; also zero agg / pooled accumulators ------------------
__global__ void __launch_bounds__(256) k_lin0(const float* __restrict__ x,
                                              const float* __restrict__ W0,
                                              const float* __restrict__ b0) {
    __shared__ float sW[11 * 64];
    __shared__ float sB[64];
    int t = threadIdx.x;
    for (int i = t; i < 11 * 64; i += 256) sW[i] = W0[i];
    if (t < 64) sB[t] = b0[t];
    __syncthreads();

    int gid = blockIdx.x * 256 + t;      // gid < NN*64 (exact multiple of 256)
    int n = gid >> 6, j = gid & 63;
    const float* xr = x + n * 11;
    float acc = sB[j];
    #pragma unroll
    for (int k = 0; k < 11; k++) acc += xr[k] * sW[k * 64 + j];
    g_bufA[gid] = acc;
    g_agg[gid] = 0.0f;
    if (gid < NG * 16) g_sums[gid] = 0.0f;
    if (gid < NG)      g_cnts[gid] = 0.0f;
}

// ---------------- edge scatter: agg[dst] += h[src], vector atomics --------------
__global__ void __launch_bounds__(256) k_scatter(const void* __restrict__ ei_,
                                                 int in_sel) {
    const float* __restrict__ h = in_sel ? g_bufB : g_bufA;
    int t = blockIdx.x * 256 + threadIdx.x;   // t < NE*16
    int e = t >> 4, c = t & 15;
    int s, d;
    if (g_is64) {
        const long long* E = (const long long*)ei_;
        s = (int)E[e];
        d = (int)E[NE + e];
    } else {
        const int* E = (const int*)ei_;
        s = E[e];
        d = E[NE + e];
    }
    float4 v = ((const float4*)h)[s * 16 + c];
    float4* p = ((float4*)g_agg) + d * 16 + c;
    asm volatile("red.global.add.v4.f32 [%0], {%1,%2,%3,%4};"
                 :: "l"(p), "f"(v.x), "f"(v.y), "f"(v.z), "f"(v.w)
                 : "memory");
}

// -------- conv: h_out = tanh(agg @ Wrel + brel + h_in @ Wroot), f32x2 math ------
// 64 nodes/block, 256 threads: thread (rg, jq) computes nodes 4rg..4rg+3, cols 4jq..+3.
// Activations stored duplicated {a,a} so LDS.64 feeds fma.rn.f32x2 directly.
__global__ void __launch_bounds__(256) k_conv(int in_sel,
                                              const float* __restrict__ Wrel,
                                              const float* __restrict__ brel,
                                              const float* __restrict__ Wroot,
                                              int out_sel, int zero_agg) {
    extern __shared__ char sm_[];
    unsigned long long* sA2 = (unsigned long long*)sm_;       // [64][65]
    unsigned long long* sH2 = sA2 + 64 * 65;                  // [64][65]
    float* sWr = (float*)(sH2 + 64 * 65);                     // [64*64]
    float* sWo = sWr + 4096;                                  // [64*64]
    float* sB  = sWo + 4096;                                  // [64]

    const float* __restrict__ hin  = in_sel  ? g_bufB : g_bufA;
    float* __restrict__       hout = out_sel ? g_bufB : g_bufA;

    int t = threadIdx.x;
    const float4* Wr4 = (const float4*)Wrel;
    const float4* Wo4 = (const float4*)Wroot;
    #pragma unroll
    for (int i = 0; i < 4; i++) {
        ((float4*)sWr)[t + i * 256] = Wr4[t + i * 256];
        ((float4*)sWo)[t + i * 256] = Wo4[t + i * 256];
    }
    if (t < 64) sB[t] = brel[t];

    int n0 = blockIdx.x * 64;
    int vlim = (NN - n0) * 64; if (vlim > 4096) vlim = 4096;  // valid floats in tile
    #pragma unroll
    for (int i = 0; i < 4; i++) {
        int off = (t + i * 256) * 4;
        if (off < vlim) {
            float4 va = *(const float4*)&g_agg[n0 * 64 + off];
            float4 vh = *(const float4*)&hin [n0 * 64 + off];
            int n = off >> 6, k = off & 63;
            unsigned long long* pa = &sA2[n * 65 + k];
            unsigned long long* ph = &sH2[n * 65 + k];
            pa[0] = dup2(va.x); pa[1] = dup2(va.y); pa[2] = dup2(va.z); pa[3] = dup2(va.w);
            ph[0] = dup2(vh.x); ph[1] = dup2(vh.y); ph[2] = dup2(vh.z); ph[3] = dup2(vh.w);
            if (zero_agg) *(float4*)&g_agg[n0 * 64 + off] = make_float4(0.f, 0.f, 0.f, 0.f);
        }
    }
    __syncthreads();

    int jq = t & 15, j0 = jq * 4;
    int rg = t >> 4, nb = rg * 4;

    ulonglong2 bias = *(ulonglong2*)&sB[j0];      // {b0,b1},{b2,b3}
    ulonglong2 acc0 = bias, acc1 = bias, acc2 = bias, acc3 = bias;

    #pragma unroll 16
    for (int k = 0; k < 64; k++) {
        ulonglong2 wr = *(ulonglong2*)&sWr[k * 64 + j0];
        ulonglong2 wo = *(ulonglong2*)&sWo[k * 64 + j0];
        unsigned long long a0 = sA2[(nb + 0) * 65 + k], h0 = sH2[(nb + 0) * 65 + k];
        unsigned long long a1 = sA2[(nb + 1) * 65 + k], h1 = sH2[(nb + 1) * 65 + k];
        unsigned long long a2 = sA2[(nb + 2) * 65 + k], h2 = sH2[(nb + 2) * 65 + k];
        unsigned long long a3 = sA2[(nb + 3) * 65 + k], h3 = sH2[(nb + 3) * 65 + k];
        acc0.x = fma2(a0, wr.x, acc0.x); acc0.x = fma2(h0, wo.x, acc0.x);
        acc0.y = fma2(a0, wr.y, acc0.y); acc0.y = fma2(h0, wo.y, acc0.y);
        acc1.x = fma2(a1, wr.x, acc1.x); acc1.x = fma2(h1, wo.x, acc1.x);
        acc1.y = fma2(a1, wr.y, acc1.y); acc1.y = fma2(h1, wo.y, acc1.y);
        acc2.x = fma2(a2, wr.x, acc2.x); acc2.x = fma2(h2, wo.x, acc2.x);
        acc2.y = fma2(a2, wr.y, acc2.y); acc2.y = fma2(h2, wo.y, acc2.y);
        acc3.x = fma2(a3, wr.x, acc3.x); acc3.x = fma2(h3, wo.x, acc3.x);
        acc3.y = fma2(a3, wr.y, acc3.y); acc3.y = fma2(h3, wo.y, acc3.y);
    }

    ulonglong2 accs[4] = {acc0, acc1, acc2, acc3};
    #pragma unroll
    for (int n = 0; n < 4; n++) {
        int node = n0 + nb + n;
        if (node < NN) {
            float2 lo = *(float2*)&accs[n].x;
            float2 hi = *(float2*)&accs[n].y;
            float4 o = make_float4(tanhf(lo.x), tanhf(lo.y), tanhf(hi.x), tanhf(hi.y));
            *(float4*)&hout[node * 64 + j0] = o;
        }
    }
}

// -------- h3 = tanh(h2 @ W3 + b3); pooled sums/counts via global atomics --------
__global__ void __launch_bounds__(256) k_lin3pool(const void* __restrict__ bat_,
                                                  const float* __restrict__ W3,
                                                  const float* __restrict__ b3) {
    __shared__ float sW[64 * 16];
    __shared__ float sB[16];
    int t = threadIdx.x;
    for (int i = t; i < 64 * 16; i += 256) sW[i] = W3[i];
    if (t < 16) sB[t] = b3[t];
    __syncthreads();

    int gid = blockIdx.x * 256 + t;    // gid < NN*16, exact multiple of 256
    int n = gid >> 4, j = gid & 15;
    const float* hr = g_bufA + n * 64;   // h2 lives in bufA
    float acc = sB[j];
    #pragma unroll
    for (int k = 0; k < 64; k++) acc += hr[k] * sW[k * 16 + j];
    float v = tanhf(acc);
    int g;
    if (g_is64) g = (int)((const long long*)bat_)[n];
    else        g = ((const int*)bat_)[n];
    atomicAdd(&g_sums[g * 16 + j], v);
    if (j == 0) atomicAdd(&g_cnts[g], 1.0f);
}

// ---------------- mean pool + NormalParamExtractor ------------------------------
__global__ void k_final(float* __restrict__ out) {
    int t = blockIdx.x * blockDim.x + threadIdx.x;
    if (t >= NG * 16) return;
    int g = t >> 4, j = t & 15;
    float m = g_sums[t] / fmaxf(g_cnts[g], 1.0f);
    if (j < 8) {
        out[g * 8 + j] = m;                       // loc
    } else {
        float s = m + 0.54132485461292192f;       // log(expm1(1.0))
        float sp = (s > 20.0f) ? s : log1pf(expf(s));
        out[NG * 8 + g * 8 + (j - 8)] = fmaxf(sp, 1e-4f);   // scale
    }
}

// ---------------- launch ---------------------------------------------------------
extern "C" void kernel_launch(void* const* d_in, const int* in_sizes, int n_in,
                              void* d_out, int out_size) {
    const float* x     = (const float*)d_in[0];
    const void*  ei    = d_in[1];
    const void*  bat   = d_in[2];
    const float* W0    = (const float*)d_in[3];
    const float* b0    = (const float*)d_in[4];
    const float* Wrel1 = (const float*)d_in[5];
    const float* brel1 = (const float*)d_in[6];
    const float* Wroot1= (const float*)d_in[7];
    const float* Wrel2 = (const float*)d_in[8];
    const float* brel2 = (const float*)d_in[9];
    const float* Wroot2= (const float*)d_in[10];
    const float* W3    = (const float*)d_in[11];
    const float* b3    = (const float*)d_in[12];
    float* out = (float*)d_out;

    const int CONV_SMEM = 2 * 64 * 65 * 8 + 2 * 4096 * 4 + 64 * 4;   // 99584 B
    cudaFuncSetAttribute(k_conv, cudaFuncAttributeMaxDynamicSharedMemorySize, CONV_SMEM);

    k_detect<<<1, 32>>>((const unsigned int*)ei);

    k_lin0<<<NN * 64 / 256, 256>>>(x, W0, b0);          // h0 -> bufA; agg/sums/cnts = 0

    k_scatter<<<NE * 16 / 256, 256>>>(ei, 0);           // agg += h0[src]
    k_conv<<<(NN + 63) / 64, 256, CONV_SMEM>>>(0, Wrel1, brel1, Wroot1, 1, 1); // h1->bufB, agg=0

    k_scatter<<<NE * 16 / 256, 256>>>(ei, 1);           // agg += h1[src]
    k_conv<<<(NN + 63) / 64, 256, CONV_SMEM>>>(1, Wrel2, brel2, Wroot2, 0, 0); // h2->bufA

    k_lin3pool<<<NN * 16 / 256, 256>>>(bat, W3, b3);    // sums/cnts
    k_final<<<(NG * 16 + 255) / 256, 256>>>(out);
}